// round 6
// baseline (speedup 1.0000x reference)
#include <cuda_runtime.h>
#include <math.h>

#define Nn      65536
#define Mm      256
#define CTRLD   1024
#define LSTMIN  3072
#define OUTD    2048
#define EPSF    1e-8f

#define PGRID   512
#define PBLK    256
#define ROWS_B  128            // rows per block
#define ROWS_W  16             // rows per warp (16 consecutive)

// ---------------- scratch ----------------
__device__ float g_mem[(size_t)Nn * Mm];
__device__ float g_simw[Nn], g_simr[Nn];
__device__ float g_wshw[Nn], g_wshr[Nn];
__device__ float g_wn2[Nn], g_wn3[Nn];
__device__ float g_gates[3 * CTRLD];
__device__ float g_o[4 * 1036];
__device__ float g_kw[4 * Mm], g_kr[4 * Mm], g_e[4 * Mm], g_a[4 * Mm];
__device__ float g_sc[80];
__device__ float g_S[32];
__device__ float g_reads[4 * Mm];
__device__ unsigned long long g_barcnt;

// ---------------- helpers ----------------
__device__ __forceinline__ float warpSum(float v) {
#pragma unroll
    for (int o = 16; o; o >>= 1) v += __shfl_down_sync(0xffffffffu, v, o);
    return v;
}
// reductions within 16-lane row groups
__device__ __forceinline__ void grpSum3(float& a, float& b, float& c) {
#pragma unroll
    for (int o = 8; o; o >>= 1) {
        a += __shfl_down_sync(0xffffffffu, a, o, 16);
        b += __shfl_down_sync(0xffffffffu, b, o, 16);
        c += __shfl_down_sync(0xffffffffu, c, o, 16);
    }
}
__device__ __forceinline__ void grpSum2(float& a, float& b) {
#pragma unroll
    for (int o = 8; o; o >>= 1) {
        a += __shfl_down_sync(0xffffffffu, a, o, 16);
        b += __shfl_down_sync(0xffffffffu, b, o, 16);
    }
}
__device__ __forceinline__ float blockSumB(float v) {
    __shared__ float sh[8];
    int lane = threadIdx.x & 31, wid = threadIdx.x >> 5;
    v = warpSum(v);
    if (lane == 0) sh[wid] = v;
    __syncthreads();
    float s = sh[0] + sh[1] + sh[2] + sh[3] + sh[4] + sh[5] + sh[6] + sh[7];
    __syncthreads();
    return s;
}
__device__ __forceinline__ float sigmoidf(float x) { return 1.f / (1.f + expf(-x)); }
__device__ __forceinline__ float softplusf(float x) {
    return x > 0.f ? x + log1pf(expf(-x)) : log1pf(expf(x));
}
__device__ __forceinline__ float dot4(float4 a, float4 b) {
    return a.x * b.x + a.y * b.y + a.z * b.z + a.w * b.w;
}
__device__ __forceinline__ float4 apply4(float4 m, float w, float4 e, float4 a) {
    float4 r;
    r.x = m.x * (1.f - w * e.x) + w * a.x;
    r.y = m.y * (1.f - w * e.y) + w * a.y;
    r.z = m.z * (1.f - w * e.z) + w * a.z;
    r.w = m.w * (1.f - w * e.w) + w * a.w;
    return r;
}
__device__ __forceinline__ void gridbar(int idx) {
    __syncthreads();
    if (threadIdx.x == 0) {
        __threadfence();
        atomicAdd(&g_barcnt, 1ULL);
        unsigned long long target = (unsigned long long)idx * PGRID;
        while (*(volatile unsigned long long*)&g_barcnt < target) __nanosleep(32);
        __threadfence();
    }
    __syncthreads();
}

// ---------------- init ----------------
__global__ void k_init() {
    int t = threadIdx.x;
    if (t == 0) g_barcnt = 0ULL;
    if (t < 32) g_S[t] = 0.f;
    g_reads[t] = 0.f;              // blockDim = 1024
}

// ---------------- addressing (cold path, exact math) ----------------
__device__ __forceinline__ void addr_phase(int rs, int t, int hr, int hw,
                                           const float* __restrict__ prev_rw,
                                           const float* __restrict__ prev_ww) {
    float sumr = 0.f, sumw = 0.f;
    if (t < ROWS_B) {
        int i = rs + t;
        int ip = (i + 1) & (Nn - 1), im = (i - 1) & (Nn - 1);
        if (hr >= 0) {
            const float* sc = g_sc + (hr * 2 + 1) * 8;
            float beta = __ldcg(&sc[0]), gg = __ldcg(&sc[1]);
            float c0 = __ldcg(&sc[2]), c1 = __ldcg(&sc[3]), c2 = __ldcg(&sc[4]);
            float gamma = __ldcg(&sc[5]);
            float gS = gg / __ldcg(&g_S[hr * 4 + 2]);
            float om = 1.f - gg;
            const float* pw = prev_rw + (size_t)hr * Nn;
            float wgp = gS * expf(beta * __ldcg(&g_simr[ip])) + om * pw[ip];
            float wgc = gS * expf(beta * __ldcg(&g_simr[i]))  + om * pw[i];
            float wgm = gS * expf(beta * __ldcg(&g_simr[im])) + om * pw[im];
            float ws = c0 * wgp + c1 * wgc + c2 * wgm;
            float wsh = powf(fmaxf(ws, 1e-12f), gamma);
            g_wshr[i] = wsh; sumr = wsh;
        }
        if (hw >= 0) {
            const float* sc = g_sc + (hw * 2) * 8;
            float beta = __ldcg(&sc[0]), gg = __ldcg(&sc[1]);
            float c0 = __ldcg(&sc[2]), c1 = __ldcg(&sc[3]), c2 = __ldcg(&sc[4]);
            float gamma = __ldcg(&sc[5]);
            float gS = gg / __ldcg(&g_S[hw * 4 + 0]);
            float om = 1.f - gg;
            const float* pw = prev_ww + (size_t)hw * Nn;
            float wgp = gS * expf(beta * __ldcg(&g_simw[ip])) + om * pw[ip];
            float wgc = gS * expf(beta * __ldcg(&g_simw[i]))  + om * pw[i];
            float wgm = gS * expf(beta * __ldcg(&g_simw[im])) + om * pw[im];
            float ws = c0 * wgp + c1 * wgc + c2 * wgm;
            float wsh = powf(fmaxf(ws, 1e-12f), gamma);
            g_wshw[i] = wsh; sumw = wsh;
        }
    }
    float sr = blockSumB(sumr);
    float sw = blockSumB(sumw);
    if (t == 0) {
        if (hr >= 0) atomicAdd(&g_S[hr * 4 + 3], sr);
        if (hw >= 0) atomicAdd(&g_S[hw * 4 + 1], sw);
    }
}

// ---------------- the one persistent kernel ----------------
__global__ void __launch_bounds__(PBLK, 4) k_all(
    const float* __restrict__ x, const float* __restrict__ prev_reads,
    const float* __restrict__ prev_h, const float* __restrict__ prev_c,
    const float* __restrict__ mem_in,
    const float* __restrict__ prev_rw, const float* __restrict__ prev_ww,
    const float* __restrict__ W_ih, const float* __restrict__ W_hh,
    const float* __restrict__ b_lstm,
    const float* __restrict__ W_out, const float* __restrict__ b_out,
    const float* __restrict__ Ww, const float* __restrict__ bw,
    const float* __restrict__ Wr, const float* __restrict__ br,
    float* __restrict__ out) {
    __shared__ float s_buf[4096];          // input staging / ctrl / out reads
    __shared__ float s_v0[Mm], s_v1[Mm], s_v2[Mm], s_v3[Mm], s_v4[Mm], s_v5[Mm];
    __shared__ float s_acc[Mm];
    __shared__ float s_red[16];
    const int b = blockIdx.x, t = threadIdx.x, lane = t & 31, wrp = t >> 5;
    const int li = lane & 15, sub = lane >> 4;     // 16-lane row groups, 2 rows/warp
    const int rs = b * ROWS_B;
    const int rw0 = rs + wrp * ROWS_W;             // warp's 16 consecutive rows
    const int gw = b * 8 + wrp;                    // global warp 0..4095

    // ===== phase 1: LSTM gates GEMV (warps 0..3071) + mem0 L2 prefetch (rest) =====
    {
        float4* si4 = (float4*)s_buf;
        for (int j = t; j < 512; j += PBLK) si4[j] = ((const float4*)x)[j];
        si4[512 + t] = ((const float4*)prev_reads)[t];
        si4[768 + t] = ((const float4*)prev_h)[t];
        __syncthreads();
        if (gw < 3072) {
            const float4* wa = (const float4*)(W_ih + (size_t)gw * LSTMIN);
            const float4* wh = (const float4*)(W_hh + (size_t)gw * CTRLD);
            float s = 0.f;
#pragma unroll 8
            for (int j = lane; j < 768; j += 32) s += dot4(wa[j], si4[j]);
#pragma unroll 8
            for (int j = lane; j < 256; j += 32) s += dot4(wh[j], si4[768 + j]);
            s = warpSum(s);
            if (lane == 0) g_gates[gw] = s + b_lstm[gw];
        } else {
            int pw = gw - 3072;               // 0..1023, 64KB each
            const float4* p = (const float4*)mem_in + (size_t)pw * 4096;
            float acc = 0.f;
#pragma unroll 8
            for (int i = lane; i < 4096; i += 32) { float4 v = __ldcg(p + i); acc += v.x + v.w; }
            if (acc == -1.2345e+37f) g_sc[79] = acc;   // never true; defeats DCE
        }
    }
    gridbar(1);

    // ===== phase 2: ctrl (per-block) + head FC GEMV =====
    {
        for (int j = t; j < CTRLD; j += PBLK) {
            float ig = __ldcg(&g_gates[j]);
            float fg = __ldcg(&g_gates[CTRLD + j]);
            float gg = __ldcg(&g_gates[2 * CTRLD + j]);
            s_buf[j] = sigmoidf(fg) * prev_c[j] + sigmoidf(ig) * tanhf(gg);
        }
        __syncthreads();
        const float4* c4 = (const float4*)s_buf;
        for (int pass = 0; pass < 2; pass++) {
            int row = (pass == 0) ? gw : (4096 + gw);
            if (row < 4144) {
                int hd = row / 1036, k = row % 1036;
                const float* wrow; float bias;
                if (k < 774) { wrow = Ww + ((size_t)hd * 774 + k) * CTRLD; bias = bw[hd * 774 + k]; }
                else { int kk = k - 774; wrow = Wr + ((size_t)hd * 262 + kk) * CTRLD; bias = br[hd * 262 + kk]; }
                const float4* w4 = (const float4*)wrow;
                float s = 0.f;
#pragma unroll 8
                for (int j = lane; j < 256; j += 32) s += dot4(w4[j], c4[j]);
                s = warpSum(s);
                if (lane == 0) g_o[row] = s + bias;
            }
        }
    }
    gridbar(2);

    // ===== phase 3: derive (blocks 0-7) + local head0 key + pass0 sims =====
    {
        if (b < 8) {
            int hh = b >> 1, role = b & 1;
            const float* o = g_o + hh * 1036 + (role ? 774 : 0);
            float kv = tanhf(__ldcg(&o[t]));
            (role ? g_kr : g_kw)[hh * Mm + t] = kv;
            if (!role) {
                g_e[hh * Mm + t] = sigmoidf(__ldcg(&o[262 + t]));
                g_a[hh * Mm + t] = tanhf(__ldcg(&o[518 + t]));
            }
            float ss = blockSumB(kv * kv);
            if (t == 0) {
                float* sc = g_sc + b * 8;
                sc[0] = softplusf(__ldcg(&o[256]));
                sc[1] = sigmoidf(__ldcg(&o[257]));
                float s0 = __ldcg(&o[258]), s1 = __ldcg(&o[259]), s2 = __ldcg(&o[260]);
                float mx = fmaxf(s0, fmaxf(s1, s2));
                float e0 = expf(s0 - mx), e1 = expf(s1 - mx), e2 = expf(s2 - mx);
                float es = e0 + e1 + e2;
                sc[2] = e0 / es; sc[3] = e1 / es; sc[4] = e2 / es;
                sc[5] = 1.f + softplusf(__ldcg(&o[261]));
                sc[6] = sqrtf(ss);
            }
        }
        // local head-0 write key (bit-identical to derive's)
        float kv = tanhf(__ldcg(&g_o[t]));
        s_v0[t] = kv;
        float kn = sqrtf(blockSumB(kv * kv));
        float beta0 = softplusf(__ldcg(&g_o[256]));
        __syncthreads();
        const float4* k4 = (const float4*)s_v0;
        float ess = 0.f;
        for (int it = 0; it < 8; it++) {
            int r = rw0 + it * 2 + sub;
            const float4* row = (const float4*)(mem_in + (size_t)r * Mm);
            float dot = 0.f, ss2 = 0.f;
#pragma unroll
            for (int j = 0; j < 4; j++) {
                int idx = li + 16 * j;
                float4 m = row[idx];
                dot += dot4(m, k4[idx]);
                ss2 += dot4(m, m);
            }
            grpSum2(dot, ss2);
            if (li == 0) {
                float sim = __fdividef(dot, sqrtf(ss2) * kn + EPSF);
                g_simw[r] = sim;
                ess += __expf(beta0 * sim);
            }
        }
        ess += __shfl_down_sync(0xffffffffu, ess, 16);
        if (lane == 0) s_red[wrp] = ess;
        __syncthreads();
        if (t == 0) {
            float s = 0.f;
            for (int w = 0; w < 8; w++) s += s_red[w];
            atomicAdd(&g_S[0], s);
        }
    }
    gridbar(3);
    addr_phase(rs, t, -1, 0, prev_rw, prev_ww);
    gridbar(4);

    // ===== U0: mem0 -> write mem1; sims kr0 / kw1 (no racc) =====
    {
        s_v0[t] = __ldcg(&g_e[t]);  s_v1[t] = __ldcg(&g_a[t]);
        s_v2[t] = __ldcg(&g_kr[t]); s_v3[t] = __ldcg(&g_kw[Mm + t]);
        __syncthreads();
        float invS2w = 1.f / (__ldcg(&g_S[1]) + EPSF);
        float beta_r = __ldcg(&g_sc[1 * 8 + 0]), kn_r = __ldcg(&g_sc[1 * 8 + 6]);
        float beta_w = __ldcg(&g_sc[2 * 8 + 0]), kn_w = __ldcg(&g_sc[2 * 8 + 6]);
        const float4* e4 = (const float4*)s_v0, *a4 = (const float4*)s_v1;
        const float4* kr4 = (const float4*)s_v2, *kw4 = (const float4*)s_v3;
        float er = 0.f, ew = 0.f;
        for (int it = 0; it < 8; it++) {
            int r = rw0 + it * 2 + sub;
            float w = g_wshw[r] * invS2w;
            const float4* row = (const float4*)(mem_in + (size_t)r * Mm);
            float4* dst = (float4*)(g_mem + (size_t)r * Mm);
            float4 m[4];
#pragma unroll
            for (int j = 0; j < 4; j++) m[j] = row[li + 16 * j];
            float dr = 0.f, ss = 0.f, dw = 0.f;
#pragma unroll
            for (int j = 0; j < 4; j++) {
                int idx = li + 16 * j;
                float4 nm = apply4(m[j], w, e4[idx], a4[idx]);
                dst[idx] = nm;
                dr += dot4(nm, kr4[idx]); ss += dot4(nm, nm); dw += dot4(nm, kw4[idx]);
            }
            grpSum3(dr, ss, dw);
            if (li == 0) {
                float nrm = sqrtf(ss);
                float simr = __fdividef(dr, nrm * kn_r + EPSF); g_simr[r] = simr; er += __expf(beta_r * simr);
                float simw = __fdividef(dw, nrm * kn_w + EPSF); g_simw[r] = simw; ew += __expf(beta_w * simw);
            }
        }
        er += __shfl_down_sync(0xffffffffu, er, 16);
        ew += __shfl_down_sync(0xffffffffu, ew, 16);
        if (lane == 0) { s_red[wrp] = er; s_red[8 + wrp] = ew; }
        __syncthreads();
        if (t == 0) {
            float sr = 0.f, sw = 0.f;
            for (int w2 = 0; w2 < 8; w2++) { sr += s_red[w2]; sw += s_red[8 + w2]; }
            atomicAdd(&g_S[2], sr); atomicAdd(&g_S[4], sw);
        }
    }
    gridbar(5);
    addr_phase(rs, t, 0, 1, prev_rw, prev_ww);
    gridbar(6);

    // ===== U1: mem1 -> write mem2; reads[0]; sims kr1 / kw2 =====
    {
        s_v0[t] = __ldcg(&g_e[Mm + t]);  s_v1[t] = __ldcg(&g_a[Mm + t]);
        s_v2[t] = __ldcg(&g_kr[Mm + t]); s_v3[t] = __ldcg(&g_kw[2 * Mm + t]);
        s_acc[t] = 0.f;
        __syncthreads();
        float invS2w = 1.f / (__ldcg(&g_S[5]) + EPSF);
        float invS2r = 1.f / (__ldcg(&g_S[3]) + EPSF);
        float beta_r = __ldcg(&g_sc[3 * 8 + 0]), kn_r = __ldcg(&g_sc[3 * 8 + 6]);
        float beta_w = __ldcg(&g_sc[4 * 8 + 0]), kn_w = __ldcg(&g_sc[4 * 8 + 6]);
        const float4* e4 = (const float4*)s_v0, *a4 = (const float4*)s_v1;
        const float4* kr4 = (const float4*)s_v2, *kw4 = (const float4*)s_v3;
        float4 racc[4];
#pragma unroll
        for (int j = 0; j < 4; j++) racc[j] = make_float4(0, 0, 0, 0);
        float er = 0.f, ew = 0.f;
        for (int it = 0; it < 8; it++) {
            int r = rw0 + it * 2 + sub;
            float w = g_wshw[r] * invS2w;
            float wp = g_wshr[r] * invS2r;
            float4* dst = (float4*)(g_mem + (size_t)r * Mm);
            float4 m[4];
#pragma unroll
            for (int j = 0; j < 4; j++) m[j] = dst[li + 16 * j];
            float dr = 0.f, ss = 0.f, dw = 0.f;
#pragma unroll
            for (int j = 0; j < 4; j++) {
                int idx = li + 16 * j;
                racc[j].x += wp * m[j].x; racc[j].y += wp * m[j].y;
                racc[j].z += wp * m[j].z; racc[j].w += wp * m[j].w;
                float4 nm = apply4(m[j], w, e4[idx], a4[idx]);
                dst[idx] = nm;
                dr += dot4(nm, kr4[idx]); ss += dot4(nm, nm); dw += dot4(nm, kw4[idx]);
            }
            grpSum3(dr, ss, dw);
            if (li == 0) {
                float nrm = sqrtf(ss);
                float simr = __fdividef(dr, nrm * kn_r + EPSF); g_simr[r] = simr; er += __expf(beta_r * simr);
                float simw = __fdividef(dw, nrm * kn_w + EPSF); g_simw[r] = simw; ew += __expf(beta_w * simw);
            }
        }
        er += __shfl_down_sync(0xffffffffu, er, 16);
        ew += __shfl_down_sync(0xffffffffu, ew, 16);
        if (lane == 0) { s_red[wrp] = er; s_red[8 + wrp] = ew; }
#pragma unroll
        for (int j = 0; j < 4; j++) {
            racc[j].x += __shfl_down_sync(0xffffffffu, racc[j].x, 16);
            racc[j].y += __shfl_down_sync(0xffffffffu, racc[j].y, 16);
            racc[j].z += __shfl_down_sync(0xffffffffu, racc[j].z, 16);
            racc[j].w += __shfl_down_sync(0xffffffffu, racc[j].w, 16);
        }
        if (sub == 0) {
#pragma unroll
            for (int j = 0; j < 4; j++) {
                int c4 = (li + 16 * j) * 4;
                atomicAdd(&s_acc[c4 + 0], racc[j].x); atomicAdd(&s_acc[c4 + 1], racc[j].y);
                atomicAdd(&s_acc[c4 + 2], racc[j].z); atomicAdd(&s_acc[c4 + 3], racc[j].w);
            }
        }
        __syncthreads();
        if (t == 0) {
            float sr = 0.f, sw = 0.f;
            for (int w2 = 0; w2 < 8; w2++) { sr += s_red[w2]; sw += s_red[8 + w2]; }
            atomicAdd(&g_S[6], sr); atomicAdd(&g_S[8], sw);
        }
        atomicAdd(&g_reads[0 * Mm + t], s_acc[t]);
    }
    gridbar(7);
    addr_phase(rs, t, 1, 2, prev_rw, prev_ww);
    gridbar(8);

    // ===== U2: read mem2 (no write); reads[1]; sims kr2 / kw3 on mem3; save w2 =====
    {
        s_v0[t] = __ldcg(&g_e[2 * Mm + t]);  s_v1[t] = __ldcg(&g_a[2 * Mm + t]);
        s_v2[t] = __ldcg(&g_kr[2 * Mm + t]); s_v3[t] = __ldcg(&g_kw[3 * Mm + t]);
        s_acc[t] = 0.f;
        __syncthreads();
        float invS2w = 1.f / (__ldcg(&g_S[9]) + EPSF);
        float invS2r = 1.f / (__ldcg(&g_S[7]) + EPSF);
        float beta_r = __ldcg(&g_sc[5 * 8 + 0]), kn_r = __ldcg(&g_sc[5 * 8 + 6]);
        float beta_w = __ldcg(&g_sc[6 * 8 + 0]), kn_w = __ldcg(&g_sc[6 * 8 + 6]);
        const float4* e4 = (const float4*)s_v0, *a4 = (const float4*)s_v1;
        const float4* kr4 = (const float4*)s_v2, *kw4 = (const float4*)s_v3;
        float4 racc[4];
#pragma unroll
        for (int j = 0; j < 4; j++) racc[j] = make_float4(0, 0, 0, 0);
        float er = 0.f, ew = 0.f;
        for (int it = 0; it < 8; it++) {
            int r = rw0 + it * 2 + sub;
            float w = g_wshw[r] * invS2w;
            if (li == 0) g_wn2[r] = w;
            float wp = g_wshr[r] * invS2r;
            const float4* row = (const float4*)(g_mem + (size_t)r * Mm);
            float4 m[4];
#pragma unroll
            for (int j = 0; j < 4; j++) m[j] = row[li + 16 * j];
            float dr = 0.f, ss = 0.f, dw = 0.f;
#pragma unroll
            for (int j = 0; j < 4; j++) {
                int idx = li + 16 * j;
                racc[j].x += wp * m[j].x; racc[j].y += wp * m[j].y;
                racc[j].z += wp * m[j].z; racc[j].w += wp * m[j].w;
                float4 nm = apply4(m[j], w, e4[idx], a4[idx]);
                dr += dot4(nm, kr4[idx]); ss += dot4(nm, nm); dw += dot4(nm, kw4[idx]);
            }
            grpSum3(dr, ss, dw);
            if (li == 0) {
                float nrm = sqrtf(ss);
                float simr = __fdividef(dr, nrm * kn_r + EPSF); g_simr[r] = simr; er += __expf(beta_r * simr);
                float simw = __fdividef(dw, nrm * kn_w + EPSF); g_simw[r] = simw; ew += __expf(beta_w * simw);
            }
        }
        er += __shfl_down_sync(0xffffffffu, er, 16);
        ew += __shfl_down_sync(0xffffffffu, ew, 16);
        if (lane == 0) { s_red[wrp] = er; s_red[8 + wrp] = ew; }
#pragma unroll
        for (int j = 0; j < 4; j++) {
            racc[j].x += __shfl_down_sync(0xffffffffu, racc[j].x, 16);
            racc[j].y += __shfl_down_sync(0xffffffffu, racc[j].y, 16);
            racc[j].z += __shfl_down_sync(0xffffffffu, racc[j].z, 16);
            racc[j].w += __shfl_down_sync(0xffffffffu, racc[j].w, 16);
        }
        if (sub == 0) {
#pragma unroll
            for (int j = 0; j < 4; j++) {
                int c4 = (li + 16 * j) * 4;
                atomicAdd(&s_acc[c4 + 0], racc[j].x); atomicAdd(&s_acc[c4 + 1], racc[j].y);
                atomicAdd(&s_acc[c4 + 2], racc[j].z); atomicAdd(&s_acc[c4 + 3], racc[j].w);
            }
        }
        __syncthreads();
        if (t == 0) {
            float sr = 0.f, sw = 0.f;
            for (int w2 = 0; w2 < 8; w2++) { sr += s_red[w2]; sw += s_red[8 + w2]; }
            atomicAdd(&g_S[10], sr); atomicAdd(&g_S[12], sw);
        }
        atomicAdd(&g_reads[1 * Mm + t], s_acc[t]);
    }
    gridbar(9);
    addr_phase(rs, t, 2, 3, prev_rw, prev_ww);
    gridbar(10);

    // ===== U3: read mem2; apply w2 then w3; reads[2] on mem3; sim kr3 on mem4 =====
    {
        s_v0[t] = __ldcg(&g_e[2 * Mm + t]);  s_v1[t] = __ldcg(&g_a[2 * Mm + t]);
        s_v4[t] = __ldcg(&g_e[3 * Mm + t]);  s_v5[t] = __ldcg(&g_a[3 * Mm + t]);
        s_v2[t] = __ldcg(&g_kr[3 * Mm + t]);
        s_acc[t] = 0.f;
        __syncthreads();
        float invS2w = 1.f / (__ldcg(&g_S[13]) + EPSF);
        float invS2r = 1.f / (__ldcg(&g_S[11]) + EPSF);
        float beta_r = __ldcg(&g_sc[7 * 8 + 0]), kn_r = __ldcg(&g_sc[7 * 8 + 6]);
        const float4* e24 = (const float4*)s_v0, *a24 = (const float4*)s_v1;
        const float4* e34 = (const float4*)s_v4, *a34 = (const float4*)s_v5;
        const float4* kr4 = (const float4*)s_v2;
        float4 racc[4];
#pragma unroll
        for (int j = 0; j < 4; j++) racc[j] = make_float4(0, 0, 0, 0);
        float er = 0.f;
        for (int it = 0; it < 8; it++) {
            int r = rw0 + it * 2 + sub;
            float w2 = g_wn2[r];
            float w3 = g_wshw[r] * invS2w;
            if (li == 0) g_wn3[r] = w3;
            float wp = g_wshr[r] * invS2r;
            const float4* row = (const float4*)(g_mem + (size_t)r * Mm);
            float4 m[4];
#pragma unroll
            for (int j = 0; j < 4; j++) m[j] = row[li + 16 * j];
            float dr = 0.f, ss = 0.f;
#pragma unroll
            for (int j = 0; j < 4; j++) {
                int idx = li + 16 * j;
                float4 m3 = apply4(m[j], w2, e24[idx], a24[idx]);          // mem3
                racc[j].x += wp * m3.x; racc[j].y += wp * m3.y;
                racc[j].z += wp * m3.z; racc[j].w += wp * m3.w;
                float4 m4 = apply4(m3, w3, e34[idx], a34[idx]);            // mem4
                dr += dot4(m4, kr4[idx]); ss += dot4(m4, m4);
            }
            grpSum2(dr, ss);
            if (li == 0) {
                float simr = __fdividef(dr, sqrtf(ss) * kn_r + EPSF);
                g_simr[r] = simr; er += __expf(beta_r * simr);
            }
        }
        er += __shfl_down_sync(0xffffffffu, er, 16);
        if (lane == 0) s_red[wrp] = er;
#pragma unroll
        for (int j = 0; j < 4; j++) {
            racc[j].x += __shfl_down_sync(0xffffffffu, racc[j].x, 16);
            racc[j].y += __shfl_down_sync(0xffffffffu, racc[j].y, 16);
            racc[j].z += __shfl_down_sync(0xffffffffu, racc[j].z, 16);
            racc[j].w += __shfl_down_sync(0xffffffffu, racc[j].w, 16);
        }
        if (sub == 0) {
#pragma unroll
            for (int j = 0; j < 4; j++) {
                int c4 = (li + 16 * j) * 4;
                atomicAdd(&s_acc[c4 + 0], racc[j].x); atomicAdd(&s_acc[c4 + 1], racc[j].y);
                atomicAdd(&s_acc[c4 + 2], racc[j].z); atomicAdd(&s_acc[c4 + 3], racc[j].w);
            }
        }
        __syncthreads();
        if (t == 0) {
            float sr = 0.f;
            for (int w2 = 0; w2 < 8; w2++) sr += s_red[w2];
            atomicAdd(&g_S[14], sr);
        }
        atomicAdd(&g_reads[2 * Mm + t], s_acc[t]);
    }
    gridbar(11);
    addr_phase(rs, t, 3, -1, prev_rw, prev_ww);
    gridbar(12);

    // ===== FINAL: reads[3] on mem4 = apply(w2, w3) over mem2 =====
    {
        // s_v0/s_v1 (e2,a2), s_v4/s_v5 (e3,a3) still loaded from U3
        s_acc[t] = 0.f;
        __syncthreads();
        float invS2r = 1.f / (__ldcg(&g_S[15]) + EPSF);
        const float4* e24 = (const float4*)s_v0, *a24 = (const float4*)s_v1;
        const float4* e34 = (const float4*)s_v4, *a34 = (const float4*)s_v5;
        float4 racc[4];
#pragma unroll
        for (int j = 0; j < 4; j++) racc[j] = make_float4(0, 0, 0, 0);
        for (int it = 0; it < 8; it++) {
            int r = rw0 + it * 2 + sub;
            float w2 = g_wn2[r], w3 = g_wn3[r];
            float wr = g_wshr[r] * invS2r;
            const float4* row = (const float4*)(g_mem + (size_t)r * Mm);
            float4 m[4];
#pragma unroll
            for (int j = 0; j < 4; j++) m[j] = row[li + 16 * j];
#pragma unroll
            for (int j = 0; j < 4; j++) {
                int idx = li + 16 * j;
                float4 m3 = apply4(m[j], w2, e24[idx], a24[idx]);
                float4 m4 = apply4(m3, w3, e34[idx], a34[idx]);
                racc[j].x += wr * m4.x; racc[j].y += wr * m4.y;
                racc[j].z += wr * m4.z; racc[j].w += wr * m4.w;
            }
        }
#pragma unroll
        for (int j = 0; j < 4; j++) {
            racc[j].x += __shfl_down_sync(0xffffffffu, racc[j].x, 16);
            racc[j].y += __shfl_down_sync(0xffffffffu, racc[j].y, 16);
            racc[j].z += __shfl_down_sync(0xffffffffu, racc[j].z, 16);
            racc[j].w += __shfl_down_sync(0xffffffffu, racc[j].w, 16);
        }
        if (sub == 0) {
#pragma unroll
            for (int j = 0; j < 4; j++) {
                int c4 = (li + 16 * j) * 4;
                atomicAdd(&s_acc[c4 + 0], racc[j].x); atomicAdd(&s_acc[c4 + 1], racc[j].y);
                atomicAdd(&s_acc[c4 + 2], racc[j].z); atomicAdd(&s_acc[c4 + 3], racc[j].w);
            }
        }
        __syncthreads();
        atomicAdd(&g_reads[3 * Mm + t], s_acc[t]);
    }
    gridbar(13);

    // ===== OUT: warp-per-row (blocks 0..255) =====
    if (b < 256) {
        for (int j = t; j < CTRLD; j += PBLK) s_buf[j] = __ldcg(&g_reads[j]);
        __syncthreads();
        int row = b * 8 + wrp;               // 0..2047
        const float4* w4 = (const float4*)(W_out + (size_t)row * CTRLD);
        const float4* r4 = (const float4*)s_buf;
        float s = 0.f;
#pragma unroll 8
        for (int j = lane; j < 256; j += 32) s += dot4(w4[j], r4[j]);
        s = warpSum(s);
        if (lane == 0) out[row] = s + b_out[row];
    }
}

// ---------------- launch ----------------
extern "C" void kernel_launch(void* const* d_in, const int* in_sizes, int n_in,
                              void* d_out, int out_size) {
    const float* x          = (const float*)d_in[0];
    const float* prev_reads = (const float*)d_in[1];
    const float* prev_h     = (const float*)d_in[2];
    const float* prev_c     = (const float*)d_in[3];
    const float* memory     = (const float*)d_in[4];
    const float* prev_rw    = (const float*)d_in[5];
    const float* prev_ww    = (const float*)d_in[6];
    const float* W_ih       = (const float*)d_in[7];
    const float* W_hh       = (const float*)d_in[8];
    const float* b_lstm     = (const float*)d_in[9];
    const float* W_out      = (const float*)d_in[10];
    const float* b_out      = (const float*)d_in[11];
    const float* Ww         = (const float*)d_in[12];
    const float* bw         = (const float*)d_in[13];
    const float* Wr         = (const float*)d_in[14];
    const float* br         = (const float*)d_in[15];
    float* out = (float*)d_out;

    k_init<<<1, 1024>>>();
    k_all<<<PGRID, PBLK>>>(x, prev_reads, prev_h, prev_c, memory, prev_rw, prev_ww,
                           W_ih, W_hh, b_lstm, W_out, b_out, Ww, bw, Wr, br, out);
}

// round 7
// speedup vs baseline: 1.3687x; 1.3687x over previous
#include <cuda_runtime.h>
#include <math.h>

#define Nn      65536
#define Mm      256
#define CTRLD   1024
#define LSTMIN  3072
#define OUTD    2048
#define EPSF    1e-8f

#define PGRID   592            // 4 blocks per SM * 148 SMs (full residency)
#define PBLK    256
#define NWARP   8

// ---------------- scratch ----------------
__device__ float g_mem[(size_t)Nn * Mm];
__device__ float g_simw[Nn], g_simr[Nn];
__device__ float g_wshw[Nn], g_wshr[Nn];
__device__ float g_wn2[Nn], g_wn3[Nn];
__device__ float g_gates[3 * CTRLD];
__device__ float g_o[4 * 1036];
__device__ float g_kw[4 * Mm], g_kr[4 * Mm], g_e[4 * Mm], g_a[4 * Mm];
__device__ float g_sc[80];
__device__ float g_S[32];
__device__ float g_reads[4 * Mm];
__device__ unsigned long long g_barcnt;

// ---------------- helpers ----------------
__device__ __forceinline__ float warpSum(float v) {
#pragma unroll
    for (int o = 16; o; o >>= 1) v += __shfl_down_sync(0xffffffffu, v, o);
    return v;
}
__device__ __forceinline__ void warpSum3(float& a, float& b, float& c) {
#pragma unroll
    for (int o = 16; o; o >>= 1) {
        a += __shfl_down_sync(0xffffffffu, a, o);
        b += __shfl_down_sync(0xffffffffu, b, o);
        c += __shfl_down_sync(0xffffffffu, c, o);
    }
}
__device__ __forceinline__ void warpSum2(float& a, float& b) {
#pragma unroll
    for (int o = 16; o; o >>= 1) {
        a += __shfl_down_sync(0xffffffffu, a, o);
        b += __shfl_down_sync(0xffffffffu, b, o);
    }
}
__device__ __forceinline__ float blockSumB(float v) {
    __shared__ float sh[8];
    int lane = threadIdx.x & 31, wid = threadIdx.x >> 5;
    v = warpSum(v);
    if (lane == 0) sh[wid] = v;
    __syncthreads();
    float s = sh[0] + sh[1] + sh[2] + sh[3] + sh[4] + sh[5] + sh[6] + sh[7];
    __syncthreads();
    return s;
}
__device__ __forceinline__ float sigmoidf(float x) { return 1.f / (1.f + expf(-x)); }
__device__ __forceinline__ float softplusf(float x) {
    return x > 0.f ? x + log1pf(expf(-x)) : log1pf(expf(x));
}
__device__ __forceinline__ float dot4(float4 a, float4 b) {
    return a.x * b.x + a.y * b.y + a.z * b.z + a.w * b.w;
}
__device__ __forceinline__ float4 apply4(float4 m, float w, float4 e, float4 a) {
    float4 r;
    r.x = m.x * (1.f - w * e.x) + w * a.x;
    r.y = m.y * (1.f - w * e.y) + w * a.y;
    r.z = m.z * (1.f - w * e.z) + w * a.z;
    r.w = m.w * (1.f - w * e.w) + w * a.w;
    return r;
}
__device__ __forceinline__ int rowStart(int b) {
    return (int)(((long long)b << 16) / PGRID);
}
__device__ __forceinline__ void gridbar(int idx) {
    __syncthreads();
    if (threadIdx.x == 0) {
        __threadfence();
        atomicAdd(&g_barcnt, 1ULL);
        unsigned long long target = (unsigned long long)idx * PGRID;
        while (*(volatile unsigned long long*)&g_barcnt < target) __nanosleep(32);
        __threadfence();
    }
    __syncthreads();
}

// ---------------- init ----------------
__global__ void k_init() {
    int t = threadIdx.x;
    if (t == 0) g_barcnt = 0ULL;
    if (t < 32) g_S[t] = 0.f;
    g_reads[t] = 0.f;              // blockDim = 1024
}

// ---------------- addressing (cold path, exact math) ----------------
__device__ __forceinline__ void addr_phase(int rs, int re, int t, int hr, int hw,
                                           const float* __restrict__ prev_rw,
                                           const float* __restrict__ prev_ww) {
    float sumr = 0.f, sumw = 0.f;
    int i = rs + t;
    if (i < re) {
        int ip = (i + 1) & (Nn - 1), im = (i - 1) & (Nn - 1);
        if (hr >= 0) {
            const float* sc = g_sc + (hr * 2 + 1) * 8;
            float beta = __ldcg(&sc[0]), gg = __ldcg(&sc[1]);
            float c0 = __ldcg(&sc[2]), c1 = __ldcg(&sc[3]), c2 = __ldcg(&sc[4]);
            float gamma = __ldcg(&sc[5]);
            float gS = gg / __ldcg(&g_S[hr * 4 + 2]);
            float om = 1.f - gg;
            const float* pw = prev_rw + (size_t)hr * Nn;
            float wgp = gS * expf(beta * __ldcg(&g_simr[ip])) + om * pw[ip];
            float wgc = gS * expf(beta * __ldcg(&g_simr[i]))  + om * pw[i];
            float wgm = gS * expf(beta * __ldcg(&g_simr[im])) + om * pw[im];
            float ws = c0 * wgp + c1 * wgc + c2 * wgm;
            float wsh = powf(fmaxf(ws, 1e-12f), gamma);
            g_wshr[i] = wsh; sumr = wsh;
        }
        if (hw >= 0) {
            const float* sc = g_sc + (hw * 2) * 8;
            float beta = __ldcg(&sc[0]), gg = __ldcg(&sc[1]);
            float c0 = __ldcg(&sc[2]), c1 = __ldcg(&sc[3]), c2 = __ldcg(&sc[4]);
            float gamma = __ldcg(&sc[5]);
            float gS = gg / __ldcg(&g_S[hw * 4 + 0]);
            float om = 1.f - gg;
            const float* pw = prev_ww + (size_t)hw * Nn;
            float wgp = gS * expf(beta * __ldcg(&g_simw[ip])) + om * pw[ip];
            float wgc = gS * expf(beta * __ldcg(&g_simw[i]))  + om * pw[i];
            float wgm = gS * expf(beta * __ldcg(&g_simw[im])) + om * pw[im];
            float ws = c0 * wgp + c1 * wgc + c2 * wgm;
            float wsh = powf(fmaxf(ws, 1e-12f), gamma);
            g_wshw[i] = wsh; sumw = wsh;
        }
    }
    float sr = blockSumB(sumr);
    float sw = blockSumB(sumw);
    if (t == 0) {
        if (hr >= 0) atomicAdd(&g_S[hr * 4 + 3], sr);
        if (hw >= 0) atomicAdd(&g_S[hw * 4 + 1], sw);
    }
}

// ---------------- the one persistent kernel ----------------
__global__ void __launch_bounds__(PBLK, 4) k_all(
    const float* __restrict__ x, const float* __restrict__ prev_reads,
    const float* __restrict__ prev_h, const float* __restrict__ prev_c,
    const float* __restrict__ mem_in,
    const float* __restrict__ prev_rw, const float* __restrict__ prev_ww,
    const float* __restrict__ W_ih, const float* __restrict__ W_hh,
    const float* __restrict__ b_lstm,
    const float* __restrict__ W_out, const float* __restrict__ b_out,
    const float* __restrict__ Ww, const float* __restrict__ bw,
    const float* __restrict__ Wr, const float* __restrict__ br,
    float* __restrict__ out) {
    __shared__ float s_buf[4096];
    __shared__ float s_acc[Mm];
    __shared__ float s_red[16];
    const int b = blockIdx.x, t = threadIdx.x, lane = t & 31, wrp = t >> 5;
    const int rs = rowStart(b), re = rowStart(b + 1);
    const int gw = b * NWARP + wrp;           // global warp id 0..4735

    // ===== phase 1: LSTM gates (warps 0..3071) + mem0 L2 prefetch (rest) =====
    {
        float4* si4 = (float4*)s_buf;
        for (int j = t; j < 512; j += PBLK) si4[j] = ((const float4*)x)[j];
        si4[512 + t] = ((const float4*)prev_reads)[t];
        si4[768 + t] = ((const float4*)prev_h)[t];
        __syncthreads();
        if (gw < 3072) {
            const float4* wa = (const float4*)(W_ih + (size_t)gw * LSTMIN);
            const float4* wh = (const float4*)(W_hh + (size_t)gw * CTRLD);
            float s = 0.f;
#pragma unroll 8
            for (int j = lane; j < 768; j += 32) s += dot4(wa[j], si4[j]);
#pragma unroll 8
            for (int j = lane; j < 256; j += 32) s += dot4(wh[j], si4[768 + j]);
            s = warpSum(s);
            if (lane == 0) g_gates[gw] = s + b_lstm[gw];
        } else {
            int pw = gw - 3072;               // 0..1663
            const int TOT4 = Nn * Mm / 4;     // 4194304
            int start = pw * 2522;
            int end = start + 2522; if (end > TOT4) end = TOT4;
            const float4* p = (const float4*)mem_in;
            float acc = 0.f;
            for (int i = start + lane; i < end; i += 32) { float4 v = __ldcg(p + i); acc += v.x + v.w; }
            if (acc == -1.2345e+37f) g_sc[79] = acc;   // never true; defeats DCE
        }
    }
    gridbar(1);

    // ===== phase 2: ctrl (per-block) + head FC GEMV (single pass) =====
    {
        for (int j = t; j < CTRLD; j += PBLK) {
            float ig = __ldcg(&g_gates[j]);
            float fg = __ldcg(&g_gates[CTRLD + j]);
            float gg = __ldcg(&g_gates[2 * CTRLD + j]);
            s_buf[j] = sigmoidf(fg) * prev_c[j] + sigmoidf(ig) * tanhf(gg);
        }
        __syncthreads();
        if (gw < 4144) {
            const float4* c4 = (const float4*)s_buf;
            int hd = gw / 1036, k = gw % 1036;
            const float* wrow; float bias;
            if (k < 774) { wrow = Ww + ((size_t)hd * 774 + k) * CTRLD; bias = bw[hd * 774 + k]; }
            else { int kk = k - 774; wrow = Wr + ((size_t)hd * 262 + kk) * CTRLD; bias = br[hd * 262 + kk]; }
            const float4* w4 = (const float4*)wrow;
            float s = 0.f;
#pragma unroll 8
            for (int j = lane; j < 256; j += 32) s += dot4(w4[j], c4[j]);
            s = warpSum(s);
            if (lane == 0) g_o[gw] = s + bias;
        }
    }
    gridbar(2);

    // ===== phase 3: derive (blocks 0-7) + local head0 key + pass0 sims =====
    {
        if (b < 8) {
            int hh = b >> 1, role = b & 1;
            const float* o = g_o + hh * 1036 + (role ? 774 : 0);
            float kv = tanhf(__ldcg(&o[t]));
            (role ? g_kr : g_kw)[hh * Mm + t] = kv;
            if (!role) {
                g_e[hh * Mm + t] = sigmoidf(__ldcg(&o[262 + t]));
                g_a[hh * Mm + t] = tanhf(__ldcg(&o[518 + t]));
            }
            float ss = blockSumB(kv * kv);
            if (t == 0) {
                float* sc = g_sc + b * 8;
                sc[0] = softplusf(__ldcg(&o[256]));
                sc[1] = sigmoidf(__ldcg(&o[257]));
                float s0 = __ldcg(&o[258]), s1 = __ldcg(&o[259]), s2 = __ldcg(&o[260]);
                float mx = fmaxf(s0, fmaxf(s1, s2));
                float e0 = expf(s0 - mx), e1 = expf(s1 - mx), e2 = expf(s2 - mx);
                float es = e0 + e1 + e2;
                sc[2] = e0 / es; sc[3] = e1 / es; sc[4] = e2 / es;
                sc[5] = 1.f + softplusf(__ldcg(&o[261]));
                sc[6] = sqrtf(ss);
            }
        }
        __syncthreads();
        // local head-0 write key (bit-identical to derive's)
        float kv = tanhf(__ldcg(&g_o[t]));
        s_buf[t] = kv;
        float kn = sqrtf(blockSumB(kv * kv));
        float beta0 = softplusf(__ldcg(&g_o[256]));
        __syncthreads();
        float4 k0 = ((const float4*)s_buf)[lane], k1 = ((const float4*)s_buf)[lane + 32];
        float ess = 0.f;
        for (int r = rs + wrp; r < re; r += NWARP) {
            const float4* row = (const float4*)(mem_in + (size_t)r * Mm);
            float4 m0 = row[lane], m1 = row[lane + 32];
            float dot = dot4(m0, k0) + dot4(m1, k1);
            float ss2 = dot4(m0, m0) + dot4(m1, m1);
            warpSum2(dot, ss2);
            if (lane == 0) {
                float sim = __fdividef(dot, sqrtf(ss2) * kn + EPSF);
                g_simw[r] = sim;
                ess += __expf(beta0 * sim);
            }
        }
        if (lane == 0) s_red[wrp] = ess;
        __syncthreads();
        if (t == 0) {
            float s = 0.f;
            for (int w = 0; w < 8; w++) s += s_red[w];
            atomicAdd(&g_S[0], s);
        }
    }
    gridbar(3);
    addr_phase(rs, re, t, -1, 0, prev_rw, prev_ww);
    gridbar(4);

    // ===== U0: mem0 -> write mem1; sims kr0 / kw1 =====
    {
        float invS2w = 1.f / (__ldcg(&g_S[1]) + EPSF);
        float beta_r = __ldcg(&g_sc[1 * 8 + 0]), kn_r = __ldcg(&g_sc[1 * 8 + 6]);
        float beta_w = __ldcg(&g_sc[2 * 8 + 0]), kn_w = __ldcg(&g_sc[2 * 8 + 6]);
        float4 e0 = __ldcg((const float4*)g_e + lane),        e1 = __ldcg((const float4*)g_e + lane + 32);
        float4 a0 = __ldcg((const float4*)g_a + lane),        a1 = __ldcg((const float4*)g_a + lane + 32);
        float4 kr0 = __ldcg((const float4*)g_kr + lane),      kr1 = __ldcg((const float4*)g_kr + lane + 32);
        float4 kw0 = __ldcg((const float4*)(g_kw + Mm) + lane), kw1 = __ldcg((const float4*)(g_kw + Mm) + lane + 32);
        float er = 0.f, ew = 0.f;
        for (int r = rs + wrp; r < re; r += NWARP) {
            float w = g_wshw[r] * invS2w;
            const float4* row = (const float4*)(mem_in + (size_t)r * Mm);
            float4* dst = (float4*)(g_mem + (size_t)r * Mm);
            float4 m0 = row[lane], m1 = row[lane + 32];
            float4 n0 = apply4(m0, w, e0, a0), n1 = apply4(m1, w, e1, a1);
            dst[lane] = n0; dst[lane + 32] = n1;
            float dr = dot4(n0, kr0) + dot4(n1, kr1);
            float ss = dot4(n0, n0) + dot4(n1, n1);
            float dw = dot4(n0, kw0) + dot4(n1, kw1);
            warpSum3(dr, ss, dw);
            if (lane == 0) {
                float nrm = sqrtf(ss);
                float simr = __fdividef(dr, nrm * kn_r + EPSF); g_simr[r] = simr; er += __expf(beta_r * simr);
                float simw = __fdividef(dw, nrm * kn_w + EPSF); g_simw[r] = simw; ew += __expf(beta_w * simw);
            }
        }
        if (lane == 0) { s_red[wrp] = er; s_red[8 + wrp] = ew; }
        __syncthreads();
        if (t == 0) {
            float sr = 0.f, sw = 0.f;
            for (int w2 = 0; w2 < 8; w2++) { sr += s_red[w2]; sw += s_red[8 + w2]; }
            atomicAdd(&g_S[2], sr); atomicAdd(&g_S[4], sw);
        }
    }
    gridbar(5);
    addr_phase(rs, re, t, 0, 1, prev_rw, prev_ww);
    gridbar(6);

    // ===== U1: mem1 -> write mem2; reads[0]; sims kr1 / kw2 =====
    {
        float invS2w = 1.f / (__ldcg(&g_S[5]) + EPSF);
        float invS2r = 1.f / (__ldcg(&g_S[3]) + EPSF);
        float beta_r = __ldcg(&g_sc[3 * 8 + 0]), kn_r = __ldcg(&g_sc[3 * 8 + 6]);
        float beta_w = __ldcg(&g_sc[4 * 8 + 0]), kn_w = __ldcg(&g_sc[4 * 8 + 6]);
        float4 e0 = __ldcg((const float4*)(g_e + Mm) + lane),  e1 = __ldcg((const float4*)(g_e + Mm) + lane + 32);
        float4 a0 = __ldcg((const float4*)(g_a + Mm) + lane),  a1 = __ldcg((const float4*)(g_a + Mm) + lane + 32);
        float4 kr0 = __ldcg((const float4*)(g_kr + Mm) + lane), kr1 = __ldcg((const float4*)(g_kr + Mm) + lane + 32);
        float4 kw0 = __ldcg((const float4*)(g_kw + 2 * Mm) + lane), kw1 = __ldcg((const float4*)(g_kw + 2 * Mm) + lane + 32);
        float4 racc0 = make_float4(0, 0, 0, 0), racc1 = make_float4(0, 0, 0, 0);
        s_acc[t] = 0.f;
        __syncthreads();
        float er = 0.f, ew = 0.f;
        for (int r = rs + wrp; r < re; r += NWARP) {
            float w = g_wshw[r] * invS2w;
            float wp = g_wshr[r] * invS2r;
            float4* dst = (float4*)(g_mem + (size_t)r * Mm);
            float4 m0 = dst[lane], m1 = dst[lane + 32];
            racc0.x += wp * m0.x; racc0.y += wp * m0.y; racc0.z += wp * m0.z; racc0.w += wp * m0.w;
            racc1.x += wp * m1.x; racc1.y += wp * m1.y; racc1.z += wp * m1.z; racc1.w += wp * m1.w;
            float4 n0 = apply4(m0, w, e0, a0), n1 = apply4(m1, w, e1, a1);
            dst[lane] = n0; dst[lane + 32] = n1;
            float dr = dot4(n0, kr0) + dot4(n1, kr1);
            float ss = dot4(n0, n0) + dot4(n1, n1);
            float dw = dot4(n0, kw0) + dot4(n1, kw1);
            warpSum3(dr, ss, dw);
            if (lane == 0) {
                float nrm = sqrtf(ss);
                float simr = __fdividef(dr, nrm * kn_r + EPSF); g_simr[r] = simr; er += __expf(beta_r * simr);
                float simw = __fdividef(dw, nrm * kn_w + EPSF); g_simw[r] = simw; ew += __expf(beta_w * simw);
            }
        }
        if (lane == 0) { s_red[wrp] = er; s_red[8 + wrp] = ew; }
        atomicAdd(&s_acc[4 * lane + 0], racc0.x); atomicAdd(&s_acc[4 * lane + 1], racc0.y);
        atomicAdd(&s_acc[4 * lane + 2], racc0.z); atomicAdd(&s_acc[4 * lane + 3], racc0.w);
        atomicAdd(&s_acc[128 + 4 * lane + 0], racc1.x); atomicAdd(&s_acc[128 + 4 * lane + 1], racc1.y);
        atomicAdd(&s_acc[128 + 4 * lane + 2], racc1.z); atomicAdd(&s_acc[128 + 4 * lane + 3], racc1.w);
        __syncthreads();
        if (t == 0) {
            float sr = 0.f, sw = 0.f;
            for (int w2 = 0; w2 < 8; w2++) { sr += s_red[w2]; sw += s_red[8 + w2]; }
            atomicAdd(&g_S[6], sr); atomicAdd(&g_S[8], sw);
        }
        atomicAdd(&g_reads[0 * Mm + t], s_acc[t]);
    }
    gridbar(7);
    addr_phase(rs, re, t, 1, 2, prev_rw, prev_ww);
    gridbar(8);

    // ===== U2: read mem2 (no write); reads[1]; sims kr2 / kw3 on mem3; save w2 =====
    {
        float invS2w = 1.f / (__ldcg(&g_S[9]) + EPSF);
        float invS2r = 1.f / (__ldcg(&g_S[7]) + EPSF);
        float beta_r = __ldcg(&g_sc[5 * 8 + 0]), kn_r = __ldcg(&g_sc[5 * 8 + 6]);
        float beta_w = __ldcg(&g_sc[6 * 8 + 0]), kn_w = __ldcg(&g_sc[6 * 8 + 6]);
        float4 e0 = __ldcg((const float4*)(g_e + 2 * Mm) + lane),  e1 = __ldcg((const float4*)(g_e + 2 * Mm) + lane + 32);
        float4 a0 = __ldcg((const float4*)(g_a + 2 * Mm) + lane),  a1 = __ldcg((const float4*)(g_a + 2 * Mm) + lane + 32);
        float4 kr0 = __ldcg((const float4*)(g_kr + 2 * Mm) + lane), kr1 = __ldcg((const float4*)(g_kr + 2 * Mm) + lane + 32);
        float4 kw0 = __ldcg((const float4*)(g_kw + 3 * Mm) + lane), kw1 = __ldcg((const float4*)(g_kw + 3 * Mm) + lane + 32);
        float4 racc0 = make_float4(0, 0, 0, 0), racc1 = make_float4(0, 0, 0, 0);
        s_acc[t] = 0.f;
        __syncthreads();
        float er = 0.f, ew = 0.f;
        for (int r = rs + wrp; r < re; r += NWARP) {
            float w = g_wshw[r] * invS2w;
            if (lane == 0) g_wn2[r] = w;
            float wp = g_wshr[r] * invS2r;
            const float4* row = (const float4*)(g_mem + (size_t)r * Mm);
            float4 m0 = row[lane], m1 = row[lane + 32];
            racc0.x += wp * m0.x; racc0.y += wp * m0.y; racc0.z += wp * m0.z; racc0.w += wp * m0.w;
            racc1.x += wp * m1.x; racc1.y += wp * m1.y; racc1.z += wp * m1.z; racc1.w += wp * m1.w;
            float4 n0 = apply4(m0, w, e0, a0), n1 = apply4(m1, w, e1, a1);
            float dr = dot4(n0, kr0) + dot4(n1, kr1);
            float ss = dot4(n0, n0) + dot4(n1, n1);
            float dw = dot4(n0, kw0) + dot4(n1, kw1);
            warpSum3(dr, ss, dw);
            if (lane == 0) {
                float nrm = sqrtf(ss);
                float simr = __fdividef(dr, nrm * kn_r + EPSF); g_simr[r] = simr; er += __expf(beta_r * simr);
                float simw = __fdividef(dw, nrm * kn_w + EPSF); g_simw[r] = simw; ew += __expf(beta_w * simw);
            }
        }
        if (lane == 0) { s_red[wrp] = er; s_red[8 + wrp] = ew; }
        atomicAdd(&s_acc[4 * lane + 0], racc0.x); atomicAdd(&s_acc[4 * lane + 1], racc0.y);
        atomicAdd(&s_acc[4 * lane + 2], racc0.z); atomicAdd(&s_acc[4 * lane + 3], racc0.w);
        atomicAdd(&s_acc[128 + 4 * lane + 0], racc1.x); atomicAdd(&s_acc[128 + 4 * lane + 1], racc1.y);
        atomicAdd(&s_acc[128 + 4 * lane + 2], racc1.z); atomicAdd(&s_acc[128 + 4 * lane + 3], racc1.w);
        __syncthreads();
        if (t == 0) {
            float sr = 0.f, sw = 0.f;
            for (int w2 = 0; w2 < 8; w2++) { sr += s_red[w2]; sw += s_red[8 + w2]; }
            atomicAdd(&g_S[10], sr); atomicAdd(&g_S[12], sw);
        }
        atomicAdd(&g_reads[1 * Mm + t], s_acc[t]);
    }
    gridbar(9);
    addr_phase(rs, re, t, 2, 3, prev_rw, prev_ww);
    gridbar(10);

    // ===== U3: read mem2; apply w2 then w3; reads[2] on mem3; sim kr3 on mem4 =====
    {
        float invS2w = 1.f / (__ldcg(&g_S[13]) + EPSF);
        float invS2r = 1.f / (__ldcg(&g_S[11]) + EPSF);
        float beta_r = __ldcg(&g_sc[7 * 8 + 0]), kn_r = __ldcg(&g_sc[7 * 8 + 6]);
        float4 e20 = __ldcg((const float4*)(g_e + 2 * Mm) + lane), e21 = __ldcg((const float4*)(g_e + 2 * Mm) + lane + 32);
        float4 a20 = __ldcg((const float4*)(g_a + 2 * Mm) + lane), a21 = __ldcg((const float4*)(g_a + 2 * Mm) + lane + 32);
        float4 e30 = __ldcg((const float4*)(g_e + 3 * Mm) + lane), e31 = __ldcg((const float4*)(g_e + 3 * Mm) + lane + 32);
        float4 a30 = __ldcg((const float4*)(g_a + 3 * Mm) + lane), a31 = __ldcg((const float4*)(g_a + 3 * Mm) + lane + 32);
        float4 kr0 = __ldcg((const float4*)(g_kr + 3 * Mm) + lane), kr1 = __ldcg((const float4*)(g_kr + 3 * Mm) + lane + 32);
        float4 racc0 = make_float4(0, 0, 0, 0), racc1 = make_float4(0, 0, 0, 0);
        s_acc[t] = 0.f;
        __syncthreads();
        float er = 0.f;
        for (int r = rs + wrp; r < re; r += NWARP) {
            float w2 = g_wn2[r];
            float w3 = g_wshw[r] * invS2w;
            if (lane == 0) g_wn3[r] = w3;
            float wp = g_wshr[r] * invS2r;
            const float4* row = (const float4*)(g_mem + (size_t)r * Mm);
            float4 m0 = row[lane], m1 = row[lane + 32];
            m0 = apply4(m0, w2, e20, a20); m1 = apply4(m1, w2, e21, a21);   // mem3
            racc0.x += wp * m0.x; racc0.y += wp * m0.y; racc0.z += wp * m0.z; racc0.w += wp * m0.w;
            racc1.x += wp * m1.x; racc1.y += wp * m1.y; racc1.z += wp * m1.z; racc1.w += wp * m1.w;
            float4 n0 = apply4(m0, w3, e30, a30), n1 = apply4(m1, w3, e31, a31);  // mem4
            float dr = dot4(n0, kr0) + dot4(n1, kr1);
            float ss = dot4(n0, n0) + dot4(n1, n1);
            warpSum2(dr, ss);
            if (lane == 0) {
                float simr = __fdividef(dr, sqrtf(ss) * kn_r + EPSF);
                g_simr[r] = simr; er += __expf(beta_r * simr);
            }
        }
        if (lane == 0) s_red[wrp] = er;
        atomicAdd(&s_acc[4 * lane + 0], racc0.x); atomicAdd(&s_acc[4 * lane + 1], racc0.y);
        atomicAdd(&s_acc[4 * lane + 2], racc0.z); atomicAdd(&s_acc[4 * lane + 3], racc0.w);
        atomicAdd(&s_acc[128 + 4 * lane + 0], racc1.x); atomicAdd(&s_acc[128 + 4 * lane + 1], racc1.y);
        atomicAdd(&s_acc[128 + 4 * lane + 2], racc1.z); atomicAdd(&s_acc[128 + 4 * lane + 3], racc1.w);
        __syncthreads();
        if (t == 0) {
            float sr = 0.f;
            for (int w2 = 0; w2 < 8; w2++) sr += s_red[w2];
            atomicAdd(&g_S[14], sr);
        }
        atomicAdd(&g_reads[2 * Mm + t], s_acc[t]);
    }
    gridbar(11);
    addr_phase(rs, re, t, 3, -1, prev_rw, prev_ww);
    gridbar(12);

    // ===== FINAL: reads[3] on mem4 = apply(w2, w3) over mem2 =====
    {
        float invS2r = 1.f / (__ldcg(&g_S[15]) + EPSF);
        float4 e20 = __ldcg((const float4*)(g_e + 2 * Mm) + lane), e21 = __ldcg((const float4*)(g_e + 2 * Mm) + lane + 32);
        float4 a20 = __ldcg((const float4*)(g_a + 2 * Mm) + lane), a21 = __ldcg((const float4*)(g_a + 2 * Mm) + lane + 32);
        float4 e30 = __ldcg((const float4*)(g_e + 3 * Mm) + lane), e31 = __ldcg((const float4*)(g_e + 3 * Mm) + lane + 32);
        float4 a30 = __ldcg((const float4*)(g_a + 3 * Mm) + lane), a31 = __ldcg((const float4*)(g_a + 3 * Mm) + lane + 32);
        float4 racc0 = make_float4(0, 0, 0, 0), racc1 = make_float4(0, 0, 0, 0);
        s_acc[t] = 0.f;
        __syncthreads();
        for (int r = rs + wrp; r < re; r += NWARP) {
            float w2 = g_wn2[r], w3 = g_wn3[r];
            float wr = g_wshr[r] * invS2r;
            const float4* row = (const float4*)(g_mem + (size_t)r * Mm);
            float4 m0 = row[lane], m1 = row[lane + 32];
            m0 = apply4(m0, w2, e20, a20); m1 = apply4(m1, w2, e21, a21);
            m0 = apply4(m0, w3, e30, a30); m1 = apply4(m1, w3, e31, a31);
            racc0.x += wr * m0.x; racc0.y += wr * m0.y; racc0.z += wr * m0.z; racc0.w += wr * m0.w;
            racc1.x += wr * m1.x; racc1.y += wr * m1.y; racc1.z += wr * m1.z; racc1.w += wr * m1.w;
        }
        atomicAdd(&s_acc[4 * lane + 0], racc0.x); atomicAdd(&s_acc[4 * lane + 1], racc0.y);
        atomicAdd(&s_acc[4 * lane + 2], racc0.z); atomicAdd(&s_acc[4 * lane + 3], racc0.w);
        atomicAdd(&s_acc[128 + 4 * lane + 0], racc1.x); atomicAdd(&s_acc[128 + 4 * lane + 1], racc1.y);
        atomicAdd(&s_acc[128 + 4 * lane + 2], racc1.z); atomicAdd(&s_acc[128 + 4 * lane + 3], racc1.w);
        __syncthreads();
        atomicAdd(&g_reads[3 * Mm + t], s_acc[t]);
    }
    gridbar(13);

    // ===== OUT: warp-per-row (blocks 0..255) =====
    if (b < 256) {
        for (int j = t; j < CTRLD; j += PBLK) s_buf[j] = __ldcg(&g_reads[j]);
        __syncthreads();
        int row = b * 8 + wrp;               // 0..2047
        const float4* w4 = (const float4*)(W_out + (size_t)row * CTRLD);
        const float4* r4 = (const float4*)s_buf;
        float s = 0.f;
#pragma unroll 8
        for (int j = lane; j < 256; j += 32) s += dot4(w4[j], r4[j]);
        s = warpSum(s);
        if (lane == 0) out[row] = s + b_out[row];
    }
}

// ---------------- launch ----------------
extern "C" void kernel_launch(void* const* d_in, const int* in_sizes, int n_in,
                              void* d_out, int out_size) {
    const float* x          = (const float*)d_in[0];
    const float* prev_reads = (const float*)d_in[1];
    const float* prev_h     = (const float*)d_in[2];
    const float* prev_c     = (const float*)d_in[3];
    const float* memory     = (const float*)d_in[4];
    const float* prev_rw    = (const float*)d_in[5];
    const float* prev_ww    = (const float*)d_in[6];
    const float* W_ih       = (const float*)d_in[7];
    const float* W_hh       = (const float*)d_in[8];
    const float* b_lstm     = (const float*)d_in[9];
    const float* W_out      = (const float*)d_in[10];
    const float* b_out      = (const float*)d_in[11];
    const float* Ww         = (const float*)d_in[12];
    const float* bw         = (const float*)d_in[13];
    const float* Wr         = (const float*)d_in[14];
    const float* br         = (const float*)d_in[15];
    float* out = (float*)d_out;

    k_init<<<1, 1024>>>();
    k_all<<<PGRID, PBLK>>>(x, prev_reads, prev_h, prev_c, memory, prev_rw, prev_ww,
                           W_ih, W_hh, b_lstm, W_out, b_out, Ww, bw, Wr, br, out);
}

// round 8
// speedup vs baseline: 1.4661x; 1.0712x over previous
#include <cuda_runtime.h>
#include <math.h>

#define Nn      65536
#define Mm      256
#define CTRLD   1024
#define LSTMIN  3072
#define OUTD    2048
#define EPSF    1e-8f

#define PGRID   592            // 4 blocks/SM * 148 SMs
#define PBLK    256
#define NWARP   8
#define MAXRB   128            // max rows per block (ceil(65536/592)=111)

// ---------------- scratch ----------------
__device__ float g_mem[(size_t)Nn * Mm];
__device__ float g_simw[Nn], g_simr[Nn];
__device__ float g_gates[3 * CTRLD];
__device__ float g_o[4 * 1036];
__device__ float g_kw[4 * Mm], g_kr[4 * Mm], g_e[4 * Mm], g_a[4 * Mm];
__device__ float g_sc[80];
__device__ float g_S[32];
__device__ float g_reads[4 * Mm];
__device__ unsigned long long g_barcnt;

// ---------------- helpers ----------------
__device__ __forceinline__ float warpSum(float v) {
#pragma unroll
    for (int o = 16; o; o >>= 1) v += __shfl_down_sync(0xffffffffu, v, o);
    return v;
}
__device__ __forceinline__ void warpSum3(float& a, float& b, float& c) {
#pragma unroll
    for (int o = 16; o; o >>= 1) {
        a += __shfl_down_sync(0xffffffffu, a, o);
        b += __shfl_down_sync(0xffffffffu, b, o);
        c += __shfl_down_sync(0xffffffffu, c, o);
    }
}
__device__ __forceinline__ void warpSum2(float& a, float& b) {
#pragma unroll
    for (int o = 16; o; o >>= 1) {
        a += __shfl_down_sync(0xffffffffu, a, o);
        b += __shfl_down_sync(0xffffffffu, b, o);
    }
}
__device__ __forceinline__ float blockSumB(float v) {
    __shared__ float sh[8];
    int lane = threadIdx.x & 31, wid = threadIdx.x >> 5;
    v = warpSum(v);
    if (lane == 0) sh[wid] = v;
    __syncthreads();
    float s = sh[0] + sh[1] + sh[2] + sh[3] + sh[4] + sh[5] + sh[6] + sh[7];
    __syncthreads();
    return s;
}
__device__ __forceinline__ float sigmoidf(float x) { return 1.f / (1.f + expf(-x)); }
__device__ __forceinline__ float softplusf(float x) {
    return x > 0.f ? x + log1pf(expf(-x)) : log1pf(expf(x));
}
__device__ __forceinline__ float dot4(float4 a, float4 b) {
    return a.x * b.x + a.y * b.y + a.z * b.z + a.w * b.w;
}
__device__ __forceinline__ float4 apply4(float4 m, float w, float4 e, float4 a) {
    float4 r;
    r.x = m.x * (1.f - w * e.x) + w * a.x;
    r.y = m.y * (1.f - w * e.y) + w * a.y;
    r.z = m.z * (1.f - w * e.z) + w * a.z;
    r.w = m.w * (1.f - w * e.w) + w * a.w;
    return r;
}
__device__ __forceinline__ int rowStart(int b) {
    return (int)(((long long)b << 16) / PGRID);
}
__device__ __forceinline__ void gridbar(int idx) {
    __syncthreads();
    if (threadIdx.x == 0) {
        __threadfence();
        atomicAdd(&g_barcnt, 1ULL);
        unsigned long long target = (unsigned long long)idx * PGRID;
        while (*(volatile unsigned long long*)&g_barcnt < target) __nanosleep(32);
        __threadfence();
    }
    __syncthreads();
}
__device__ __forceinline__ void cpa16(void* sdst, const void* gsrc) {
    unsigned s = (unsigned)__cvta_generic_to_shared(sdst);
    asm volatile("cp.async.cg.shared.global [%0], [%1], 16;" :: "r"(s), "l"(gsrc));
}
#define CPA_COMMIT() asm volatile("cp.async.commit_group;")
#define CPA_WAIT1()  asm volatile("cp.async.wait_group 1;")
#define CPA_WAIT0()  asm volatile("cp.async.wait_group 0;")

// ---------------- init ----------------
__global__ void k_init() {
    int t = threadIdx.x;
    if (t == 0) g_barcnt = 0ULL;
    if (t < 32) g_S[t] = 0.f;
    g_reads[t] = 0.f;              // blockDim = 1024
}

// ---------------- the one persistent kernel ----------------
__global__ void __launch_bounds__(PBLK, 4) k_all(
    const float* __restrict__ x, const float* __restrict__ prev_reads,
    const float* __restrict__ prev_h, const float* __restrict__ prev_c,
    const float* __restrict__ mem_in,
    const float* __restrict__ prev_rw, const float* __restrict__ prev_ww,
    const float* __restrict__ W_ih, const float* __restrict__ W_hh,
    const float* __restrict__ b_lstm,
    const float* __restrict__ W_out, const float* __restrict__ b_out,
    const float* __restrict__ Ww, const float* __restrict__ bw,
    const float* __restrict__ Wr, const float* __restrict__ br,
    float* __restrict__ out) {
    __shared__ float  s_buf[4096];
    __shared__ float4 s_stage[NWARP][2][64];
    __shared__ float  s_dr[MAXRB], s_ss[MAXRB], s_dw[MAXRB];
    __shared__ float  s_wshr[MAXRB], s_wshw[MAXRB];
    __shared__ float  s_wa[MAXRB], s_wb[MAXRB];     // normalized write / read weights
    __shared__ float  s_wn2[MAXRB], s_wn3[MAXRB];   // persisted w2, w3
    __shared__ float  s_acc[Mm];
    const int b = blockIdx.x, t = threadIdx.x, lane = t & 31, wrp = t >> 5;
    const int rs = rowStart(b), re = rowStart(b + 1);
    const int nb = re - rs;
    const int gw = b * NWARP + wrp;           // global warp id 0..4735

    // ===== phase 1: LSTM gates (warps 0..3071) + mem0 L2 prefetch (rest) =====
    {
        float4* si4 = (float4*)s_buf;
        for (int j = t; j < 512; j += PBLK) si4[j] = ((const float4*)x)[j];
        si4[512 + t] = ((const float4*)prev_reads)[t];
        si4[768 + t] = ((const float4*)prev_h)[t];
        __syncthreads();
        if (gw < 3072) {
            const float4* wa = (const float4*)(W_ih + (size_t)gw * LSTMIN);
            const float4* wh = (const float4*)(W_hh + (size_t)gw * CTRLD);
            float s = 0.f;
#pragma unroll 8
            for (int j = lane; j < 768; j += 32) s += dot4(wa[j], si4[j]);
#pragma unroll 8
            for (int j = lane; j < 256; j += 32) s += dot4(wh[j], si4[768 + j]);
            s = warpSum(s);
            if (lane == 0) g_gates[gw] = s + b_lstm[gw];
        } else {
            int pw = gw - 3072;               // 0..1663
            const int TOT4 = Nn * Mm / 4;
            int start = pw * 2522;
            int end = start + 2522; if (end > TOT4) end = TOT4;
            const float4* p = (const float4*)mem_in;
            float acc = 0.f;
            for (int i = start + lane; i < end; i += 32) { float4 v = __ldcg(p + i); acc += v.x + v.w; }
            if (acc == -1.2345e+37f) g_sc[79] = acc;   // never true; defeats DCE
        }
    }
    gridbar(1);

    // ===== phase 2: ctrl (per-block) + head FC GEMV (single pass) =====
    {
        for (int j = t; j < CTRLD; j += PBLK) {
            float ig = __ldcg(&g_gates[j]);
            float fg = __ldcg(&g_gates[CTRLD + j]);
            float gg = __ldcg(&g_gates[2 * CTRLD + j]);
            s_buf[j] = sigmoidf(fg) * prev_c[j] + sigmoidf(ig) * tanhf(gg);
        }
        __syncthreads();
        if (gw < 4144) {
            const float4* c4 = (const float4*)s_buf;
            int hd = gw / 1036, k = gw % 1036;
            const float* wrow; float bias;
            if (k < 774) { wrow = Ww + ((size_t)hd * 774 + k) * CTRLD; bias = bw[hd * 774 + k]; }
            else { int kk = k - 774; wrow = Wr + ((size_t)hd * 262 + kk) * CTRLD; bias = br[hd * 262 + kk]; }
            const float4* w4 = (const float4*)wrow;
            float s = 0.f;
#pragma unroll 8
            for (int j = lane; j < 256; j += 32) s += dot4(w4[j], c4[j]);
            s = warpSum(s);
            if (lane == 0) g_o[gw] = s + bias;
        }
    }
    gridbar(2);

    // ===== phase 3: derive (blocks 0-7) + local head0 key + pass0 sims =====
    {
        if (b < 8) {
            int hh = b >> 1, role = b & 1;
            const float* o = g_o + hh * 1036 + (role ? 774 : 0);
            float kv = tanhf(__ldcg(&o[t]));
            (role ? g_kr : g_kw)[hh * Mm + t] = kv;
            if (!role) {
                g_e[hh * Mm + t] = sigmoidf(__ldcg(&o[262 + t]));
                g_a[hh * Mm + t] = tanhf(__ldcg(&o[518 + t]));
            }
            float ss = blockSumB(kv * kv);
            if (t == 0) {
                float* sc = g_sc + b * 8;
                sc[0] = softplusf(__ldcg(&o[256]));
                sc[1] = sigmoidf(__ldcg(&o[257]));
                float s0 = __ldcg(&o[258]), s1 = __ldcg(&o[259]), s2 = __ldcg(&o[260]);
                float mx = fmaxf(s0, fmaxf(s1, s2));
                float e0 = expf(s0 - mx), e1 = expf(s1 - mx), e2 = expf(s2 - mx);
                float es = e0 + e1 + e2;
                sc[2] = e0 / es; sc[3] = e1 / es; sc[4] = e2 / es;
                sc[5] = 1.f + softplusf(__ldcg(&o[261]));
                sc[6] = sqrtf(ss);
            }
        }
        __syncthreads();
        // local head-0 write key (bit-identical to derive's)
        float kv = tanhf(__ldcg(&g_o[t]));
        s_buf[t] = kv;
        float kn = sqrtf(blockSumB(kv * kv));
        float beta0 = softplusf(__ldcg(&g_o[256]));
        __syncthreads();
        float4 k0 = ((const float4*)s_buf)[lane], k1 = ((const float4*)s_buf)[lane + 32];
        // pipelined sim pass over mem_in
        int r = rs + wrp, buf = 0;
        if (r < re) {
            const float4* row = (const float4*)(mem_in + (size_t)r * Mm);
            cpa16(&s_stage[wrp][0][lane], row + lane);
            cpa16(&s_stage[wrp][0][lane + 32], row + lane + 32);
            CPA_COMMIT();
        }
        for (; r < re; r += NWARP) {
            int rn = r + NWARP;
            if (rn < re) {
                const float4* nrow = (const float4*)(mem_in + (size_t)rn * Mm);
                cpa16(&s_stage[wrp][buf ^ 1][lane], nrow + lane);
                cpa16(&s_stage[wrp][buf ^ 1][lane + 32], nrow + lane + 32);
                CPA_COMMIT(); CPA_WAIT1();
            } else CPA_WAIT0();
            float4 m0 = s_stage[wrp][buf][lane], m1 = s_stage[wrp][buf][lane + 32];
            float dot = dot4(m0, k0) + dot4(m1, k1);
            float ss2 = dot4(m0, m0) + dot4(m1, m1);
            warpSum2(dot, ss2);
            if (lane == 0) { s_dr[r - rs] = dot; s_ss[r - rs] = ss2; }
            buf ^= 1;
        }
        __syncthreads();
        float ess = 0.f;
        if (t < nb) {
            float sim = __fdividef(s_dr[t], sqrtf(s_ss[t]) * kn + EPSF);
            g_simw[rs + t] = sim;
            ess = __expf(beta0 * sim);
        }
        float s = blockSumB(ess);
        if (t == 0) atomicAdd(&g_S[0], s);
    }
    gridbar(3);

    // ===== macro for addressing phase (writes block-local smem) =====
#define ADDR_PHASE(HR, HW)                                                          \
    {                                                                               \
        float sumr = 0.f, sumw = 0.f;                                               \
        if (t < nb) {                                                               \
            int i = rs + t;                                                         \
            int ip = (i + 1) & (Nn - 1), im = (i - 1) & (Nn - 1);                   \
            if ((HR) >= 0) {                                                        \
                const float* sc = g_sc + ((HR) * 2 + 1) * 8;                        \
                float beta = __ldcg(&sc[0]), gg = __ldcg(&sc[1]);                   \
                float c0 = __ldcg(&sc[2]), c1 = __ldcg(&sc[3]), c2 = __ldcg(&sc[4]);\
                float gamma = __ldcg(&sc[5]);                                       \
                float gS = gg / __ldcg(&g_S[(HR) * 4 + 2]);                         \
                float om = 1.f - gg;                                                \
                const float* pw = prev_rw + (size_t)(HR) * Nn;                      \
                float wgp = gS * expf(beta * __ldcg(&g_simr[ip])) + om * pw[ip];    \
                float wgc = gS * expf(beta * __ldcg(&g_simr[i]))  + om * pw[i];     \
                float wgm = gS * expf(beta * __ldcg(&g_simr[im])) + om * pw[im];    \
                float ws = c0 * wgp + c1 * wgc + c2 * wgm;                          \
                float wsh = powf(fmaxf(ws, 1e-12f), gamma);                         \
                s_wshr[t] = wsh; sumr = wsh;                                        \
            }                                                                       \
            if ((HW) >= 0) {                                                        \
                const float* sc = g_sc + ((HW) * 2) * 8;                            \
                float beta = __ldcg(&sc[0]), gg = __ldcg(&sc[1]);                   \
                float c0 = __ldcg(&sc[2]), c1 = __ldcg(&sc[3]), c2 = __ldcg(&sc[4]);\
                float gamma = __ldcg(&sc[5]);                                       \
                float gS = gg / __ldcg(&g_S[(HW) * 4 + 0]);                         \
                float om = 1.f - gg;                                                \
                const float* pw = prev_ww + (size_t)(HW) * Nn;                      \
                float wgp = gS * expf(beta * __ldcg(&g_simw[ip])) + om * pw[ip];    \
                float wgc = gS * expf(beta * __ldcg(&g_simw[i]))  + om * pw[i];     \
                float wgm = gS * expf(beta * __ldcg(&g_simw[im])) + om * pw[im];    \
                float ws = c0 * wgp + c1 * wgc + c2 * wgm;                          \
                float wsh = powf(fmaxf(ws, 1e-12f), gamma);                         \
                s_wshw[t] = wsh; sumw = wsh;                                        \
            }                                                                       \
        }                                                                           \
        float sr = blockSumB(sumr);                                                 \
        float sw = blockSumB(sumw);                                                 \
        if (t == 0) {                                                               \
            if ((HR) >= 0) atomicAdd(&g_S[(HR) * 4 + 3], sr);                       \
            if ((HW) >= 0) atomicAdd(&g_S[(HW) * 4 + 1], sw);                       \
        }                                                                           \
    }

    ADDR_PHASE(-1, 0);
    gridbar(4);

    // ===== U0: mem0 -> write mem1; sims kr0 / kw1 =====
    {
        if (t < nb) s_wa[t] = s_wshw[t] / (__ldcg(&g_S[1]) + EPSF);
        __syncthreads();
        float4 e0 = __ldcg((const float4*)g_e + lane),        e1 = __ldcg((const float4*)g_e + lane + 32);
        float4 a0 = __ldcg((const float4*)g_a + lane),        a1 = __ldcg((const float4*)g_a + lane + 32);
        float4 kr0 = __ldcg((const float4*)g_kr + lane),      kr1 = __ldcg((const float4*)g_kr + lane + 32);
        float4 kw0 = __ldcg((const float4*)(g_kw + Mm) + lane), kw1 = __ldcg((const float4*)(g_kw + Mm) + lane + 32);
        int r = rs + wrp, buf = 0;
        if (r < re) {
            const float4* row = (const float4*)(mem_in + (size_t)r * Mm);
            cpa16(&s_stage[wrp][0][lane], row + lane);
            cpa16(&s_stage[wrp][0][lane + 32], row + lane + 32);
            CPA_COMMIT();
        }
        for (; r < re; r += NWARP) {
            int rn = r + NWARP;
            if (rn < re) {
                const float4* nrow = (const float4*)(mem_in + (size_t)rn * Mm);
                cpa16(&s_stage[wrp][buf ^ 1][lane], nrow + lane);
                cpa16(&s_stage[wrp][buf ^ 1][lane + 32], nrow + lane + 32);
                CPA_COMMIT(); CPA_WAIT1();
            } else CPA_WAIT0();
            float4 m0 = s_stage[wrp][buf][lane], m1 = s_stage[wrp][buf][lane + 32];
            float w = s_wa[r - rs];
            float4 n0 = apply4(m0, w, e0, a0), n1 = apply4(m1, w, e1, a1);
            float4* dst = (float4*)(g_mem + (size_t)r * Mm);
            dst[lane] = n0; dst[lane + 32] = n1;
            float dr = dot4(n0, kr0) + dot4(n1, kr1);
            float ss = dot4(n0, n0) + dot4(n1, n1);
            float dw = dot4(n0, kw0) + dot4(n1, kw1);
            warpSum3(dr, ss, dw);
            if (lane == 0) { s_dr[r - rs] = dr; s_ss[r - rs] = ss; s_dw[r - rs] = dw; }
            buf ^= 1;
        }
        __syncthreads();
        float er = 0.f, ew = 0.f;
        if (t < nb) {
            float nrm = sqrtf(s_ss[t]);
            float beta_r = __ldcg(&g_sc[1 * 8 + 0]), kn_r = __ldcg(&g_sc[1 * 8 + 6]);
            float beta_w = __ldcg(&g_sc[2 * 8 + 0]), kn_w = __ldcg(&g_sc[2 * 8 + 6]);
            float simr = __fdividef(s_dr[t], nrm * kn_r + EPSF); g_simr[rs + t] = simr; er = __expf(beta_r * simr);
            float simw = __fdividef(s_dw[t], nrm * kn_w + EPSF); g_simw[rs + t] = simw; ew = __expf(beta_w * simw);
        }
        float sr = blockSumB(er), sw = blockSumB(ew);
        if (t == 0) { atomicAdd(&g_S[2], sr); atomicAdd(&g_S[4], sw); }
    }
    gridbar(5);
    ADDR_PHASE(0, 1);
    gridbar(6);

    // ===== U1: mem1 -> write mem2; reads[0]; sims kr1 / kw2 =====
    {
        if (t < nb) {
            s_wa[t] = s_wshw[t] / (__ldcg(&g_S[5]) + EPSF);
            s_wb[t] = s_wshr[t] / (__ldcg(&g_S[3]) + EPSF);
        }
        s_acc[t] = 0.f;
        __syncthreads();
        float4 e0 = __ldcg((const float4*)(g_e + Mm) + lane),  e1 = __ldcg((const float4*)(g_e + Mm) + lane + 32);
        float4 a0 = __ldcg((const float4*)(g_a + Mm) + lane),  a1 = __ldcg((const float4*)(g_a + Mm) + lane + 32);
        float4 kr0 = __ldcg((const float4*)(g_kr + Mm) + lane), kr1 = __ldcg((const float4*)(g_kr + Mm) + lane + 32);
        float4 kw0 = __ldcg((const float4*)(g_kw + 2 * Mm) + lane), kw1 = __ldcg((const float4*)(g_kw + 2 * Mm) + lane + 32);
        float4 racc0 = make_float4(0, 0, 0, 0), racc1 = make_float4(0, 0, 0, 0);
        int r = rs + wrp, buf = 0;
        if (r < re) {
            const float4* row = (const float4*)(g_mem + (size_t)r * Mm);
            cpa16(&s_stage[wrp][0][lane], row + lane);
            cpa16(&s_stage[wrp][0][lane + 32], row + lane + 32);
            CPA_COMMIT();
        }
        for (; r < re; r += NWARP) {
            int rn = r + NWARP;
            if (rn < re) {
                const float4* nrow = (const float4*)(g_mem + (size_t)rn * Mm);
                cpa16(&s_stage[wrp][buf ^ 1][lane], nrow + lane);
                cpa16(&s_stage[wrp][buf ^ 1][lane + 32], nrow + lane + 32);
                CPA_COMMIT(); CPA_WAIT1();
            } else CPA_WAIT0();
            float4 m0 = s_stage[wrp][buf][lane], m1 = s_stage[wrp][buf][lane + 32];
            float w = s_wa[r - rs], wp = s_wb[r - rs];
            racc0.x += wp * m0.x; racc0.y += wp * m0.y; racc0.z += wp * m0.z; racc0.w += wp * m0.w;
            racc1.x += wp * m1.x; racc1.y += wp * m1.y; racc1.z += wp * m1.z; racc1.w += wp * m1.w;
            float4 n0 = apply4(m0, w, e0, a0), n1 = apply4(m1, w, e1, a1);
            float4* dst = (float4*)(g_mem + (size_t)r * Mm);
            dst[lane] = n0; dst[lane + 32] = n1;
            float dr = dot4(n0, kr0) + dot4(n1, kr1);
            float ss = dot4(n0, n0) + dot4(n1, n1);
            float dw = dot4(n0, kw0) + dot4(n1, kw1);
            warpSum3(dr, ss, dw);
            if (lane == 0) { s_dr[r - rs] = dr; s_ss[r - rs] = ss; s_dw[r - rs] = dw; }
            buf ^= 1;
        }
        atomicAdd(&s_acc[4 * lane + 0], racc0.x); atomicAdd(&s_acc[4 * lane + 1], racc0.y);
        atomicAdd(&s_acc[4 * lane + 2], racc0.z); atomicAdd(&s_acc[4 * lane + 3], racc0.w);
        atomicAdd(&s_acc[128 + 4 * lane + 0], racc1.x); atomicAdd(&s_acc[128 + 4 * lane + 1], racc1.y);
        atomicAdd(&s_acc[128 + 4 * lane + 2], racc1.z); atomicAdd(&s_acc[128 + 4 * lane + 3], racc1.w);
        __syncthreads();
        float er = 0.f, ew = 0.f;
        if (t < nb) {
            float nrm = sqrtf(s_ss[t]);
            float beta_r = __ldcg(&g_sc[3 * 8 + 0]), kn_r = __ldcg(&g_sc[3 * 8 + 6]);
            float beta_w = __ldcg(&g_sc[4 * 8 + 0]), kn_w = __ldcg(&g_sc[4 * 8 + 6]);
            float simr = __fdividef(s_dr[t], nrm * kn_r + EPSF); g_simr[rs + t] = simr; er = __expf(beta_r * simr);
            float simw = __fdividef(s_dw[t], nrm * kn_w + EPSF); g_simw[rs + t] = simw; ew = __expf(beta_w * simw);
        }
        float sr = blockSumB(er), sw = blockSumB(ew);
        if (t == 0) { atomicAdd(&g_S[6], sr); atomicAdd(&g_S[8], sw); }
        atomicAdd(&g_reads[0 * Mm + t], s_acc[t]);
    }
    gridbar(7);
    ADDR_PHASE(1, 2);
    gridbar(8);

    // ===== U2: read mem2; reads[1]; sims kr2 / kw3 on mem3; w2 persisted =====
    {
        if (t < nb) {
            s_wn2[t] = s_wshw[t] / (__ldcg(&g_S[9]) + EPSF);
            s_wb[t]  = s_wshr[t] / (__ldcg(&g_S[7]) + EPSF);
        }
        s_acc[t] = 0.f;
        __syncthreads();
        float4 e0 = __ldcg((const float4*)(g_e + 2 * Mm) + lane),  e1 = __ldcg((const float4*)(g_e + 2 * Mm) + lane + 32);
        float4 a0 = __ldcg((const float4*)(g_a + 2 * Mm) + lane),  a1 = __ldcg((const float4*)(g_a + 2 * Mm) + lane + 32);
        float4 kr0 = __ldcg((const float4*)(g_kr + 2 * Mm) + lane), kr1 = __ldcg((const float4*)(g_kr + 2 * Mm) + lane + 32);
        float4 kw0 = __ldcg((const float4*)(g_kw + 3 * Mm) + lane), kw1 = __ldcg((const float4*)(g_kw + 3 * Mm) + lane + 32);
        float4 racc0 = make_float4(0, 0, 0, 0), racc1 = make_float4(0, 0, 0, 0);
        int r = rs + wrp, buf = 0;
        if (r < re) {
            const float4* row = (const float4*)(g_mem + (size_t)r * Mm);
            cpa16(&s_stage[wrp][0][lane], row + lane);
            cpa16(&s_stage[wrp][0][lane + 32], row + lane + 32);
            CPA_COMMIT();
        }
        for (; r < re; r += NWARP) {
            int rn = r + NWARP;
            if (rn < re) {
                const float4* nrow = (const float4*)(g_mem + (size_t)rn * Mm);
                cpa16(&s_stage[wrp][buf ^ 1][lane], nrow + lane);
                cpa16(&s_stage[wrp][buf ^ 1][lane + 32], nrow + lane + 32);
                CPA_COMMIT(); CPA_WAIT1();
            } else CPA_WAIT0();
            float4 m0 = s_stage[wrp][buf][lane], m1 = s_stage[wrp][buf][lane + 32];
            float w = s_wn2[r - rs], wp = s_wb[r - rs];
            racc0.x += wp * m0.x; racc0.y += wp * m0.y; racc0.z += wp * m0.z; racc0.w += wp * m0.w;
            racc1.x += wp * m1.x; racc1.y += wp * m1.y; racc1.z += wp * m1.z; racc1.w += wp * m1.w;
            float4 n0 = apply4(m0, w, e0, a0), n1 = apply4(m1, w, e1, a1);
            float dr = dot4(n0, kr0) + dot4(n1, kr1);
            float ss = dot4(n0, n0) + dot4(n1, n1);
            float dw = dot4(n0, kw0) + dot4(n1, kw1);
            warpSum3(dr, ss, dw);
            if (lane == 0) { s_dr[r - rs] = dr; s_ss[r - rs] = ss; s_dw[r - rs] = dw; }
            buf ^= 1;
        }
        atomicAdd(&s_acc[4 * lane + 0], racc0.x); atomicAdd(&s_acc[4 * lane + 1], racc0.y);
        atomicAdd(&s_acc[4 * lane + 2], racc0.z); atomicAdd(&s_acc[4 * lane + 3], racc0.w);
        atomicAdd(&s_acc[128 + 4 * lane + 0], racc1.x); atomicAdd(&s_acc[128 + 4 * lane + 1], racc1.y);
        atomicAdd(&s_acc[128 + 4 * lane + 2], racc1.z); atomicAdd(&s_acc[128 + 4 * lane + 3], racc1.w);
        __syncthreads();
        float er = 0.f, ew = 0.f;
        if (t < nb) {
            float nrm = sqrtf(s_ss[t]);
            float beta_r = __ldcg(&g_sc[5 * 8 + 0]), kn_r = __ldcg(&g_sc[5 * 8 + 6]);
            float beta_w = __ldcg(&g_sc[6 * 8 + 0]), kn_w = __ldcg(&g_sc[6 * 8 + 6]);
            float simr = __fdividef(s_dr[t], nrm * kn_r + EPSF); g_simr[rs + t] = simr; er = __expf(beta_r * simr);
            float simw = __fdividef(s_dw[t], nrm * kn_w + EPSF); g_simw[rs + t] = simw; ew = __expf(beta_w * simw);
        }
        float sr = blockSumB(er), sw = blockSumB(ew);
        if (t == 0) { atomicAdd(&g_S[10], sr); atomicAdd(&g_S[12], sw); }
        atomicAdd(&g_reads[1 * Mm + t], s_acc[t]);
    }
    gridbar(9);
    ADDR_PHASE(2, 3);
    gridbar(10);

    // ===== U3: read mem2; apply w2 then w3; reads[2] on mem3; sim kr3 on mem4 =====
    {
        if (t < nb) {
            s_wn3[t] = s_wshw[t] / (__ldcg(&g_S[13]) + EPSF);
            s_wb[t]  = s_wshr[t] / (__ldcg(&g_S[11]) + EPSF);
        }
        s_acc[t] = 0.f;
        __syncthreads();
        float4 e20 = __ldcg((const float4*)(g_e + 2 * Mm) + lane), e21 = __ldcg((const float4*)(g_e + 2 * Mm) + lane + 32);
        float4 a20 = __ldcg((const float4*)(g_a + 2 * Mm) + lane), a21 = __ldcg((const float4*)(g_a + 2 * Mm) + lane + 32);
        float4 e30 = __ldcg((const float4*)(g_e + 3 * Mm) + lane), e31 = __ldcg((const float4*)(g_e + 3 * Mm) + lane + 32);
        float4 a30 = __ldcg((const float4*)(g_a + 3 * Mm) + lane), a31 = __ldcg((const float4*)(g_a + 3 * Mm) + lane + 32);
        float4 kr0 = __ldcg((const float4*)(g_kr + 3 * Mm) + lane), kr1 = __ldcg((const float4*)(g_kr + 3 * Mm) + lane + 32);
        float4 racc0 = make_float4(0, 0, 0, 0), racc1 = make_float4(0, 0, 0, 0);
        int r = rs + wrp, buf = 0;
        if (r < re) {
            const float4* row = (const float4*)(g_mem + (size_t)r * Mm);
            cpa16(&s_stage[wrp][0][lane], row + lane);
            cpa16(&s_stage[wrp][0][lane + 32], row + lane + 32);
            CPA_COMMIT();
        }
        for (; r < re; r += NWARP) {
            int rn = r + NWARP;
            if (rn < re) {
                const float4* nrow = (const float4*)(g_mem + (size_t)rn * Mm);
                cpa16(&s_stage[wrp][buf ^ 1][lane], nrow + lane);
                cpa16(&s_stage[wrp][buf ^ 1][lane + 32], nrow + lane + 32);
                CPA_COMMIT(); CPA_WAIT1();
            } else CPA_WAIT0();
            float4 m0 = s_stage[wrp][buf][lane], m1 = s_stage[wrp][buf][lane + 32];
            float w2 = s_wn2[r - rs], w3 = s_wn3[r - rs], wp = s_wb[r - rs];
            m0 = apply4(m0, w2, e20, a20); m1 = apply4(m1, w2, e21, a21);   // mem3
            racc0.x += wp * m0.x; racc0.y += wp * m0.y; racc0.z += wp * m0.z; racc0.w += wp * m0.w;
            racc1.x += wp * m1.x; racc1.y += wp * m1.y; racc1.z += wp * m1.z; racc1.w += wp * m1.w;
            float4 n0 = apply4(m0, w3, e30, a30), n1 = apply4(m1, w3, e31, a31);  // mem4
            float dr = dot4(n0, kr0) + dot4(n1, kr1);
            float ss = dot4(n0, n0) + dot4(n1, n1);
            warpSum2(dr, ss);
            if (lane == 0) { s_dr[r - rs] = dr; s_ss[r - rs] = ss; }
            buf ^= 1;
        }
        atomicAdd(&s_acc[4 * lane + 0], racc0.x); atomicAdd(&s_acc[4 * lane + 1], racc0.y);
        atomicAdd(&s_acc[4 * lane + 2], racc0.z); atomicAdd(&s_acc[4 * lane + 3], racc0.w);
        atomicAdd(&s_acc[128 + 4 * lane + 0], racc1.x); atomicAdd(&s_acc[128 + 4 * lane + 1], racc1.y);
        atomicAdd(&s_acc[128 + 4 * lane + 2], racc1.z); atomicAdd(&s_acc[128 + 4 * lane + 3], racc1.w);
        __syncthreads();
        float er = 0.f;
        if (t < nb) {
            float beta_r = __ldcg(&g_sc[7 * 8 + 0]), kn_r = __ldcg(&g_sc[7 * 8 + 6]);
            float simr = __fdividef(s_dr[t], sqrtf(s_ss[t]) * kn_r + EPSF);
            g_simr[rs + t] = simr; er = __expf(beta_r * simr);
        }
        float sr = blockSumB(er);
        if (t == 0) atomicAdd(&g_S[14], sr);
        atomicAdd(&g_reads[2 * Mm + t], s_acc[t]);
    }
    gridbar(11);
    ADDR_PHASE(3, -1);
    gridbar(12);

    // ===== FINAL: reads[3] on mem4 = apply(w2, w3) over mem2 (HW-pipelined) =====
    {
        if (t < nb) s_wb[t] = s_wshr[t] / (__ldcg(&g_S[15]) + EPSF);
        s_acc[t] = 0.f;
        __syncthreads();
        float4 e20 = __ldcg((const float4*)(g_e + 2 * Mm) + lane), e21 = __ldcg((const float4*)(g_e + 2 * Mm) + lane + 32);
        float4 a20 = __ldcg((const float4*)(g_a + 2 * Mm) + lane), a21 = __ldcg((const float4*)(g_a + 2 * Mm) + lane + 32);
        float4 e30 = __ldcg((const float4*)(g_e + 3 * Mm) + lane), e31 = __ldcg((const float4*)(g_e + 3 * Mm) + lane + 32);
        float4 a30 = __ldcg((const float4*)(g_a + 3 * Mm) + lane), a31 = __ldcg((const float4*)(g_a + 3 * Mm) + lane + 32);
        float4 racc0 = make_float4(0, 0, 0, 0), racc1 = make_float4(0, 0, 0, 0);
        for (int r = rs + wrp; r < re; r += NWARP) {
            float w2 = s_wn2[r - rs], w3 = s_wn3[r - rs], wr = s_wb[r - rs];
            const float4* row = (const float4*)(g_mem + (size_t)r * Mm);
            float4 m0 = row[lane], m1 = row[lane + 32];
            m0 = apply4(m0, w2, e20, a20); m1 = apply4(m1, w2, e21, a21);
            m0 = apply4(m0, w3, e30, a30); m1 = apply4(m1, w3, e31, a31);
            racc0.x += wr * m0.x; racc0.y += wr * m0.y; racc0.z += wr * m0.z; racc0.w += wr * m0.w;
            racc1.x += wr * m1.x; racc1.y += wr * m1.y; racc1.z += wr * m1.z; racc1.w += wr * m1.w;
        }
        atomicAdd(&s_acc[4 * lane + 0], racc0.x); atomicAdd(&s_acc[4 * lane + 1], racc0.y);
        atomicAdd(&s_acc[4 * lane + 2], racc0.z); atomicAdd(&s_acc[4 * lane + 3], racc0.w);
        atomicAdd(&s_acc[128 + 4 * lane + 0], racc1.x); atomicAdd(&s_acc[128 + 4 * lane + 1], racc1.y);
        atomicAdd(&s_acc[128 + 4 * lane + 2], racc1.z); atomicAdd(&s_acc[128 + 4 * lane + 3], racc1.w);
        __syncthreads();
        atomicAdd(&g_reads[3 * Mm + t], s_acc[t]);
    }
    gridbar(13);

    // ===== OUT: warp-per-row (blocks 0..255) =====
    if (b < 256) {
        for (int j = t; j < CTRLD; j += PBLK) s_buf[j] = __ldcg(&g_reads[j]);
        __syncthreads();
        int row = b * 8 + wrp;               // 0..2047
        const float4* w4 = (const float4*)(W_out + (size_t)row * CTRLD);
        const float4* r4 = (const float4*)s_buf;
        float s = 0.f;
#pragma unroll 8
        for (int j = lane; j < 256; j += 32) s += dot4(w4[j], r4[j]);
        s = warpSum(s);
        if (lane == 0) out[row] = s + b_out[row];
    }
}

// ---------------- launch ----------------
extern "C" void kernel_launch(void* const* d_in, const int* in_sizes, int n_in,
                              void* d_out, int out_size) {
    const float* x          = (const float*)d_in[0];
    const float* prev_reads = (const float*)d_in[1];
    const float* prev_h     = (const float*)d_in[2];
    const float* prev_c     = (const float*)d_in[3];
    const float* memory     = (const float*)d_in[4];
    const float* prev_rw    = (const float*)d_in[5];
    const float* prev_ww    = (const float*)d_in[6];
    const float* W_ih       = (const float*)d_in[7];
    const float* W_hh       = (const float*)d_in[8];
    const float* b_lstm     = (const float*)d_in[9];
    const float* W_out      = (const float*)d_in[10];
    const float* b_out      = (const float*)d_in[11];
    const float* Ww         = (const float*)d_in[12];
    const float* bw         = (const float*)d_in[13];
    const float* Wr         = (const float*)d_in[14];
    const float* br         = (const float*)d_in[15];
    float* out = (float*)d_out;

    k_init<<<1, 1024>>>();
    k_all<<<PGRID, PBLK>>>(x, prev_reads, prev_h, prev_c, memory, prev_rw, prev_ww,
                           W_ih, W_hh, b_lstm, W_out, b_out, Ww, bw, Wr, br, out);
}